// round 7
// baseline (speedup 1.0000x reference)
#include <cuda_runtime.h>
#include <cuda_bf16.h>
#include <cstdint>
#include <cstddef>

// Problem constants
#define BATCH 8
#define NV    12000
#define NS    9
#define MTOT  (BATCH * NV)   // 96000
#define NPART (MTOT / 128)   // 750 m-blocks -> stats partials per layer

// Scratch (device globals; no allocation allowed)
__device__ float g_bufA[(size_t)MTOT * 256];   // 98.3 MB
__device__ float g_bufB[(size_t)MTOT * 128];   // 49.2 MB
__device__ float g_psum[NPART * 256];
__device__ float g_psq [NPART * 256];
__device__ float g_scale[256];
__device__ float g_shift[256];
__device__ float g_hmax[BATCH * 256];
__device__ int   g_is64;

// ---------------------------------------------------------------------------
// Detect whether the spiral index tensor is int64 or int32.
// ---------------------------------------------------------------------------
__global__ void detect64_kernel(const long long* __restrict__ p) {
    bool ok = true;
    for (int i = threadIdx.x; i < 2048; i += 256) {
        long long v = p[i];
        if (v < 0 || v >= NV) ok = false;
    }
    int all = __syncthreads_and(ok ? 1 : 0);
    if (threadIdx.x == 0) g_is64 = all;
}

// ---------------------------------------------------------------------------
// Gather-fused SGEMM with fused BN-apply on input (NORM) and fused BN stats
// on output: y[m, n] = sum_k act(feat)[m, k] * w[n, k]
// act(v) = NORM ? relu(v * scale[c] + shift[c]) : v
// Conv bias dropped: BatchNorm's mean subtraction cancels it exactly.
// Tiling: BM=128, BNT in {64,128}, BK=16; 256 threads; 8 x (BNT/16) microtile.
// Double-buffered SMEM: schedule per tile is
//   LDG(next) -> compute(buf p) -> STS(next -> buf 1-p) -> bar
// so gather loads have the whole FMA burst to land and only ONE barrier per
// tile is needed (R5 ncu: fma 59.4%, issue 70.9% — barrier + LDG->STS
// serialization was the residual exposure).
// __launch_bounds__(256, 2): 2 CTAs/SM (R5: occ 22.8%, regs 128, no spill).
// ---------------------------------------------------------------------------
#define BM 128
#define BK 16
#define AS_STRIDE (BM + 4)   // 132: 16B-aligned rows, reduced STS conflicts

template <int CIN, bool VEC, int BNT, bool NORM>
__global__ __launch_bounds__(256, 2)
void gemm_gather_kernel(const float* __restrict__ src,
                        const void* __restrict__ spir_raw,
                        const float* __restrict__ w,
                        const float* __restrict__ scale,
                        const float* __restrict__ shift,
                        float* __restrict__ y,
                        float* __restrict__ psum,
                        float* __restrict__ psq,
                        int N) {
    constexpr int K   = NS * CIN;
    constexpr int TN  = BNT / 16;        // columns per thread (4 or 8)
    constexpr int TG  = TN / 4;          // float4 groups per thread
    constexpr int NBB = (BK * BNT) / (4 * 256);  // B float4s per thread (1 or 2)
    __shared__ float As[2][BK * AS_STRIDE];
    __shared__ float Bs[2][BK * BNT];
    __shared__ int   sidx[BM][NS];       // pre-scaled row base: (b*NV + idx)*CIN
    __shared__ __align__(16) float s_sc[CIN];
    __shared__ __align__(16) float s_sh[CIN];

    const int tid = threadIdx.x;
    const int tx = tid & 15;             // n-dim
    const int ty = tid >> 4;             // m-dim
    const int m0 = blockIdx.x * BM;
    const int n0 = blockIdx.y * BNT;

    // Stage BN params for the input activation
    if constexpr (NORM) {
        for (int i = tid; i < CIN; i += 256) {
            s_sc[i] = scale[i];
            s_sh[i] = shift[i];
        }
    }

    // Resolve spiral indices for this row tile
    {
        const long long* s64 = (const long long*)spir_raw;
        const int*       s32 = (const int*)spir_raw;
        const int is64 = g_is64;
        for (int j = tid; j < BM * NS; j += 256) {
            int m = j / NS, s = j - m * NS;
            int gm = m0 + m;
            int b = gm / NV;
            long long e = is64 ? s64[(size_t)gm * NS + s]
                               : (long long)s32[(size_t)gm * NS + s];
            sidx[m][s] = (b * NV + (int)e) * CIN;
        }
    }
    __syncthreads();

    // Apply BN + ReLU to a gathered float4 at channel base c (c % 4 == 0)
    auto act4 = [&](float4 v, int c) -> float4 {
        if constexpr (NORM) {
            float4 sc4 = *reinterpret_cast<const float4*>(&s_sc[c]);
            float4 sh4 = *reinterpret_cast<const float4*>(&s_sh[c]);
            v.x = fmaxf(fmaf(v.x, sc4.x, sh4.x), 0.f);
            v.y = fmaxf(fmaf(v.y, sc4.y, sh4.y), 0.f);
            v.z = fmaxf(fmaf(v.z, sc4.z, sh4.z), 0.f);
            v.w = fmaxf(fmaf(v.w, sc4.w, sh4.w), 0.f);
        }
        return v;
    };

    float acc[8][TN];
#pragma unroll
    for (int i = 0; i < 8; i++)
#pragma unroll
        for (int j = 0; j < TN; j++) acc[i][j] = 0.f;

    if constexpr (VEC) {
        // -------- double-buffered, software-pipelined mainloop --------
        float4 pa[2], pbv[NBB];

        auto ldg_tile = [&](int kb) {
#pragma unroll
            for (int j = 0; j < 2; j++) {
                int i = tid + j * 256;       // 0..511
                int m = i >> 2, kq = i & 3;
                int k = kb + kq * 4;
                int s = k / CIN, c = k - s * CIN;
                pa[j] = act4(*reinterpret_cast<const float4*>(src + sidx[m][s] + c), c);
            }
#pragma unroll
            for (int j = 0; j < NBB; j++) {
                int i = tid + j * 256;
                int n = i >> 2, kq = i & 3;
                pbv[j] = *reinterpret_cast<const float4*>(
                    w + (size_t)(n0 + n) * K + kb + kq * 4);
            }
        };
        auto sts_tile = [&](int buf) {
#pragma unroll
            for (int j = 0; j < 2; j++) {
                int i = tid + j * 256;
                int m = i >> 2, kq = i & 3;
                As[buf][(kq * 4 + 0) * AS_STRIDE + m] = pa[j].x;
                As[buf][(kq * 4 + 1) * AS_STRIDE + m] = pa[j].y;
                As[buf][(kq * 4 + 2) * AS_STRIDE + m] = pa[j].z;
                As[buf][(kq * 4 + 3) * AS_STRIDE + m] = pa[j].w;
            }
#pragma unroll
            for (int j = 0; j < NBB; j++) {
                int i = tid + j * 256;
                int n = i >> 2, kq = i & 3;
                Bs[buf][(kq * 4 + 0) * BNT + n] = pbv[j].x;
                Bs[buf][(kq * 4 + 1) * BNT + n] = pbv[j].y;
                Bs[buf][(kq * 4 + 2) * BNT + n] = pbv[j].z;
                Bs[buf][(kq * 4 + 3) * BNT + n] = pbv[j].w;
            }
        };
        auto compute_tile = [&](int buf) {
#pragma unroll
            for (int kk = 0; kk < BK; kk++) {
                float a[8], bb[TN];
                {
                    float4 a0 = *reinterpret_cast<const float4*>(&As[buf][kk * AS_STRIDE + ty * 4]);
                    float4 a1 = *reinterpret_cast<const float4*>(&As[buf][kk * AS_STRIDE + 64 + ty * 4]);
                    a[0] = a0.x; a[1] = a0.y; a[2] = a0.z; a[3] = a0.w;
                    a[4] = a1.x; a[5] = a1.y; a[6] = a1.z; a[7] = a1.w;
                }
#pragma unroll
                for (int t = 0; t < TG; t++) {
                    float4 b4 = *reinterpret_cast<const float4*>(&Bs[buf][kk * BNT + t * 64 + tx * 4]);
                    bb[t * 4 + 0] = b4.x; bb[t * 4 + 1] = b4.y;
                    bb[t * 4 + 2] = b4.z; bb[t * 4 + 3] = b4.w;
                }
#pragma unroll
                for (int i = 0; i < 8; i++)
#pragma unroll
                    for (int j = 0; j < TN; j++)
                        acc[i][j] += a[i] * bb[j];
            }
        };

        // prologue: tile 0 into buffer 0
        ldg_tile(0);
        sts_tile(0);
        __syncthreads();

        int p = 0;
        for (int k0 = 0; k0 < K; k0 += BK) {
            const int kn = k0 + BK;
            if (kn < K) ldg_tile(kn);       // gathers fly under compute
            compute_tile(p);
            if (kn < K) {
                sts_tile(p ^ 1);            // write the idle buffer
                __syncthreads();            // one barrier per tile
                p ^= 1;
            }
        }
    } else {
        // ---------------- simple mainloop (L1, K = 27) ----------------
        for (int k0 = 0; k0 < K; k0 += BK) {
#pragma unroll
            for (int j = 0; j < 8; j++) {
                int i = tid + j * 256;          // 0..2047
                int m = i & 127, k = i >> 7;
                int kk = k0 + k;
                float v = 0.f;
                if (kk < K) {
                    int s = kk / CIN, c = kk - s * CIN;
                    v = src[sidx[m][s] + c];
                }
                As[0][k * AS_STRIDE + m] = v;
            }
#pragma unroll
            for (int j = 0; j < (BK * BNT) / 256; j++) {
                int i = tid + j * 256;
                int n = i & (BNT - 1), k = i / BNT;
                int kk = k0 + k;
                float v = 0.f;
                if (kk < K) v = w[(size_t)(n0 + n) * K + kk];
                Bs[0][k * BNT + n] = v;
            }
            __syncthreads();

#pragma unroll
            for (int kk = 0; kk < BK; kk++) {
                float a[8], bb[TN];
                {
                    float4 a0 = *reinterpret_cast<const float4*>(&As[0][kk * AS_STRIDE + ty * 4]);
                    float4 a1 = *reinterpret_cast<const float4*>(&As[0][kk * AS_STRIDE + 64 + ty * 4]);
                    a[0] = a0.x; a[1] = a0.y; a[2] = a0.z; a[3] = a0.w;
                    a[4] = a1.x; a[5] = a1.y; a[6] = a1.z; a[7] = a1.w;
                }
#pragma unroll
                for (int t = 0; t < TG; t++) {
                    float4 b4 = *reinterpret_cast<const float4*>(&Bs[0][kk * BNT + t * 64 + tx * 4]);
                    bb[t * 4 + 0] = b4.x; bb[t * 4 + 1] = b4.y;
                    bb[t * 4 + 2] = b4.z; bb[t * 4 + 3] = b4.w;
                }
#pragma unroll
                for (int i = 0; i < 8; i++)
#pragma unroll
                    for (int j = 0; j < TN; j++)
                        acc[i][j] += a[i] * bb[j];
            }
            __syncthreads();
        }
    }

    // ---- Store output tile (no bias: it cancels in BatchNorm) ----
#pragma unroll
    for (int i = 0; i < 8; i++) {
        int m = m0 + ((i < 4) ? (ty * 4 + i) : (64 + ty * 4 + (i - 4)));
#pragma unroll
        for (int t = 0; t < TG; t++) {
            float4 o;
            o.x = acc[i][t * 4 + 0];
            o.y = acc[i][t * 4 + 1];
            o.z = acc[i][t * 4 + 2];
            o.w = acc[i][t * 4 + 3];
            *reinterpret_cast<float4*>(&y[(size_t)m * N + n0 + t * 64 + tx * 4]) = o;
        }
    }

    // ---- Fused BN statistics: per-block column sum / sumsq partials ----
    __syncthreads();   // all compute reads of As/Bs done before scratch reuse
    {
        float s[TN], q[TN];
#pragma unroll
        for (int j = 0; j < TN; j++) { s[j] = 0.f; q[j] = 0.f; }
#pragma unroll
        for (int i = 0; i < 8; i++)
#pragma unroll
            for (int j = 0; j < TN; j++) {
                float v = acc[i][j];
                s[j] += v;
                q[j] += v * v;
            }
        float* ssum = As[0];   // 16 * BNT floats fits in As[0]
        float* ssq  = Bs[0];   // 16 * BNT floats == Bs[0] size
#pragma unroll
        for (int t = 0; t < TG; t++)
#pragma unroll
            for (int j = 0; j < 4; j++) {
                int col = t * 64 + tx * 4 + j;
                ssum[ty * BNT + col] = s[t * 4 + j];
                ssq [ty * BNT + col] = q[t * 4 + j];
            }
        __syncthreads();
        if (tid < BNT) {
            float S = 0.f, Q = 0.f;
#pragma unroll
            for (int r = 0; r < 16; r++) {
                S += ssum[r * BNT + tid];
                Q += ssq [r * BNT + tid];
            }
            psum[(size_t)blockIdx.x * N + n0 + tid] = S;
            psq [(size_t)blockIdx.x * N + n0 + tid] = Q;
        }
    }
}

// ---------------------------------------------------------------------------
// Reduce per-block partials -> BN scale/shift (fp64, deterministic)
// ---------------------------------------------------------------------------
__global__ void finalize_kernel(const float* __restrict__ psum,
                                const float* __restrict__ psq,
                                const float* __restrict__ g,
                                const float* __restrict__ bt,
                                float* __restrict__ scale,
                                float* __restrict__ shift, int N) {
    int o = threadIdx.x;
    if (o >= N) return;
    double s = 0.0, q = 0.0;
    for (int c = 0; c < NPART; c++) {
        s += psum[(size_t)c * N + o];
        q += psq [(size_t)c * N + o];
    }
    double mean = s / (double)MTOT;
    double var  = q / (double)MTOT - mean * mean;   // biased variance (ddof=0)
    float sc = g[o] * rsqrtf((float)var + 1e-5f);
    scale[o] = sc;
    shift[o] = bt[o] - (float)mean * sc;
}

// Max over vertices with fused BN+ReLU: grid (256/32, B), block (32, 8)
__global__ void maxpool_kernel(const float* __restrict__ act,
                               const float* __restrict__ scale,
                               const float* __restrict__ shift,
                               float* __restrict__ hmax) {
    const int tx = threadIdx.x, ty = threadIdx.y;
    const int o = blockIdx.x * 32 + tx;
    const int b = blockIdx.y;
    const float sc = scale[o], sh = shift[o];
    float m = -1e30f;
    for (int v = ty; v < NV; v += 8)
        m = fmaxf(m, fmaf(act[((size_t)b * NV + v) * 256 + o], sc, sh));
    __shared__ float shm[8][32];
    shm[ty][tx] = m;
    __syncthreads();
    if (ty == 0) {
#pragma unroll
        for (int i = 1; i < 8; i++) m = fmaxf(m, shm[i][tx]);
        hmax[b * 256 + o] = fmaxf(m, 0.f);
    }
}

// out[b, j] = sum_o hmax[b, o] * pw[j, o] + pb[j]
__global__ void final_linear_kernel(const float* __restrict__ hmax,
                                    const float* __restrict__ pw,
                                    const float* __restrict__ pb,
                                    float* __restrict__ out) {
    __shared__ float sh[BATCH * 256];
    for (int i = threadIdx.x; i < BATCH * 256; i += 256) sh[i] = hmax[i];
    __syncthreads();
    int j = threadIdx.x;
    float acc[BATCH];
#pragma unroll
    for (int b = 0; b < BATCH; b++) acc[b] = pb[j];
    for (int o = 0; o < 256; o++) {
        float wv = pw[j * 256 + o];
#pragma unroll
        for (int b = 0; b < BATCH; b++) acc[b] += sh[b * 256 + o] * wv;
    }
#pragma unroll
    for (int b = 0; b < BATCH; b++) out[b * 256 + j] = acc[b];
}

// ---------------------------------------------------------------------------
extern "C" void kernel_launch(void* const* d_in, const int* in_sizes, int n_in,
                              void* d_out, int out_size) {
    const float* x    = (const float*)d_in[0];
    const void*  spir = d_in[1];
    const float* w1 = (const float*)d_in[2];
    const float* g1 = (const float*)d_in[4];
    const float* t1 = (const float*)d_in[5];
    const float* w2 = (const float*)d_in[6];
    const float* g2 = (const float*)d_in[8];
    const float* t2 = (const float*)d_in[9];
    const float* w3 = (const float*)d_in[10];
    const float* g3 = (const float*)d_in[12];
    const float* t3 = (const float*)d_in[13];
    const float* pw = (const float*)d_in[14];
    const float* pb = (const float*)d_in[15];

    float *bufA, *bufB, *psum, *psq, *scale, *shift, *hmax;
    cudaGetSymbolAddress((void**)&bufA,  g_bufA);
    cudaGetSymbolAddress((void**)&bufB,  g_bufB);
    cudaGetSymbolAddress((void**)&psum,  g_psum);
    cudaGetSymbolAddress((void**)&psq,   g_psq);
    cudaGetSymbolAddress((void**)&scale, g_scale);
    cudaGetSymbolAddress((void**)&shift, g_shift);
    cudaGetSymbolAddress((void**)&hmax,  g_hmax);

    detect64_kernel<<<1, 256>>>((const long long*)spir);

    const int mblocks = MTOT / BM;   // 750

    // ---- Layer 1: 3 -> 64 (K = 27), raw input ----
    gemm_gather_kernel<3, false, 64, false><<<dim3(mblocks, 1), 256>>>(
        x, spir, w1, nullptr, nullptr, bufA, psum, psq, 64);
    finalize_kernel<<<1, 64>>>(psum, psq, g1, t1, scale, shift, 64);

    // ---- Layer 2: 64 -> 128 (K = 576), BN1+ReLU fused into gather ----
    gemm_gather_kernel<64, true, 128, true><<<dim3(mblocks, 1), 256>>>(
        bufA, spir, w2, scale, shift, bufB, psum, psq, 128);
    finalize_kernel<<<1, 128>>>(psum, psq, g2, t2, scale, shift, 128);

    // ---- Layer 3: 128 -> 256 (K = 1152), BN2+ReLU fused into gather ----
    gemm_gather_kernel<128, true, 128, true><<<dim3(mblocks, 2), 256>>>(
        bufB, spir, w3, scale, shift, bufA, psum, psq, 256);
    finalize_kernel<<<1, 256>>>(psum, psq, g3, t3, scale, shift, 256);

    // ---- Max pool (BN3+ReLU fused) + final linear ----
    maxpool_kernel<<<dim3(8, BATCH), dim3(32, 8)>>>(bufA, scale, shift, hmax);
    final_linear_kernel<<<1, 256>>>(hmax, pw, pb, (float*)d_out);
}

// round 10
// speedup vs baseline: 1.4638x; 1.4638x over previous
#include <cuda_runtime.h>
#include <cuda_bf16.h>
#include <cstdint>
#include <cstddef>
#include <cstring>

// Problem constants
#define BATCH 8
#define NV    12000
#define NS    9
#define MTOT  (BATCH * NV)   // 96000
#define NPART (MTOT / 128)   // 750 m-blocks -> stats partials (SIMT layers)
#define L3NCH 120            // stats chunks for the L3 standalone pass
#define MKI   3456           // L3 interleaved K' = 3 * 1152

// Scratch (device globals; no allocation allowed)
__device__ float g_bufA[(size_t)MTOT * 256];   // 98.3 MB
__device__ float g_bufB[(size_t)MTOT * 128];   // 49.2 MB
__device__ __nv_bfloat16 g_a3[(size_t)MTOT * 384];   // 73.7 MB (hi,hi,lo interleave)
__device__ __nv_bfloat16 g_w3i[256 * MKI];           // 1.77 MB (hi,lo,hi interleave)
__device__ float g_psum[NPART * 256];
__device__ float g_psq [NPART * 256];
__device__ float g_scale[256];
__device__ float g_shift[256];
__device__ float g_hmax[BATCH * 256];
__device__ int   g_is64;

__device__ __forceinline__ uint32_t smem_u32(const void* p) {
    uint32_t a;
    asm("{ .reg .u64 t; cvta.to.shared.u64 t, %1; cvt.u32.u64 %0, t; }"
        : "=r"(a) : "l"(p));
    return a;
}

// ---------------------------------------------------------------------------
// Detect whether the spiral index tensor is int64 or int32.
// ---------------------------------------------------------------------------
__global__ void detect64_kernel(const long long* __restrict__ p) {
    bool ok = true;
    for (int i = threadIdx.x; i < 2048; i += 256) {
        long long v = p[i];
        if (v < 0 || v >= NV) ok = false;
    }
    int all = __syncthreads_and(ok ? 1 : 0);
    if (threadIdx.x == 0) g_is64 = all;
}

// ---------------------------------------------------------------------------
// SIMT gather-fused SGEMM (R5-proven version) — layers 1 and 2.
// ---------------------------------------------------------------------------
#define BM 128
#define BK 16
#define AS_STRIDE (BM + 4)

template <int CIN, bool VEC, int BNT, bool NORM>
__global__ __launch_bounds__(256, 2)
void gemm_gather_kernel(const float* __restrict__ src,
                        const void* __restrict__ spir_raw,
                        const float* __restrict__ w,
                        const float* __restrict__ scale,
                        const float* __restrict__ shift,
                        float* __restrict__ y,
                        float* __restrict__ psum,
                        float* __restrict__ psq,
                        int N) {
    constexpr int K   = NS * CIN;
    constexpr int TN  = BNT / 16;
    constexpr int TG  = TN / 4;
    constexpr int NBB = (BK * BNT) / (4 * 256);
    __shared__ float As[BK * AS_STRIDE];
    __shared__ float Bs[BK * BNT];
    __shared__ int   sidx[BM][NS];
    __shared__ __align__(16) float s_sc[CIN];
    __shared__ __align__(16) float s_sh[CIN];

    const int tid = threadIdx.x;
    const int tx = tid & 15;
    const int ty = tid >> 4;
    const int m0 = blockIdx.x * BM;
    const int n0 = blockIdx.y * BNT;

    if constexpr (NORM) {
        for (int i = tid; i < CIN; i += 256) {
            s_sc[i] = scale[i];
            s_sh[i] = shift[i];
        }
    }
    {
        const long long* s64 = (const long long*)spir_raw;
        const int*       s32 = (const int*)spir_raw;
        const int is64 = g_is64;
        for (int j = tid; j < BM * NS; j += 256) {
            int m = j / NS, s = j - m * NS;
            int gm = m0 + m;
            int b = gm / NV;
            long long e = is64 ? s64[(size_t)gm * NS + s]
                               : (long long)s32[(size_t)gm * NS + s];
            sidx[m][s] = (b * NV + (int)e) * CIN;
        }
    }
    __syncthreads();

    auto act4 = [&](float4 v, int c) -> float4 {
        if constexpr (NORM) {
            float4 sc4 = *reinterpret_cast<const float4*>(&s_sc[c]);
            float4 sh4 = *reinterpret_cast<const float4*>(&s_sh[c]);
            v.x = fmaxf(fmaf(v.x, sc4.x, sh4.x), 0.f);
            v.y = fmaxf(fmaf(v.y, sc4.y, sh4.y), 0.f);
            v.z = fmaxf(fmaf(v.z, sc4.z, sh4.z), 0.f);
            v.w = fmaxf(fmaf(v.w, sc4.w, sh4.w), 0.f);
        }
        return v;
    };

    float acc[8][TN];
#pragma unroll
    for (int i = 0; i < 8; i++)
#pragma unroll
        for (int j = 0; j < TN; j++) acc[i][j] = 0.f;

    if constexpr (VEC) {
        float4 pa[2], pbv[NBB];
        {
#pragma unroll
            for (int j = 0; j < 2; j++) {
                int i = tid + j * 256;
                int m = i >> 2, kq = i & 3;
                int k = kq * 4;
                int s = k / CIN, c = k - s * CIN;
                pa[j] = act4(*reinterpret_cast<const float4*>(src + sidx[m][s] + c), c);
            }
#pragma unroll
            for (int j = 0; j < NBB; j++) {
                int i = tid + j * 256;
                int n = i >> 2, kq = i & 3;
                pbv[j] = *reinterpret_cast<const float4*>(
                    w + (size_t)(n0 + n) * K + kq * 4);
            }
        }
        for (int k0 = 0; k0 < K; k0 += BK) {
#pragma unroll
            for (int j = 0; j < 2; j++) {
                int i = tid + j * 256;
                int m = i >> 2, kq = i & 3;
                As[(kq * 4 + 0) * AS_STRIDE + m] = pa[j].x;
                As[(kq * 4 + 1) * AS_STRIDE + m] = pa[j].y;
                As[(kq * 4 + 2) * AS_STRIDE + m] = pa[j].z;
                As[(kq * 4 + 3) * AS_STRIDE + m] = pa[j].w;
            }
#pragma unroll
            for (int j = 0; j < NBB; j++) {
                int i = tid + j * 256;
                int n = i >> 2, kq = i & 3;
                Bs[(kq * 4 + 0) * BNT + n] = pbv[j].x;
                Bs[(kq * 4 + 1) * BNT + n] = pbv[j].y;
                Bs[(kq * 4 + 2) * BNT + n] = pbv[j].z;
                Bs[(kq * 4 + 3) * BNT + n] = pbv[j].w;
            }
            __syncthreads();

            const int kn = k0 + BK;
            if (kn < K) {
#pragma unroll
                for (int j = 0; j < 2; j++) {
                    int i = tid + j * 256;
                    int m = i >> 2, kq = i & 3;
                    int k = kn + kq * 4;
                    int s = k / CIN, c = k - s * CIN;
                    pa[j] = act4(*reinterpret_cast<const float4*>(src + sidx[m][s] + c), c);
                }
#pragma unroll
                for (int j = 0; j < NBB; j++) {
                    int i = tid + j * 256;
                    int n = i >> 2, kq = i & 3;
                    pbv[j] = *reinterpret_cast<const float4*>(
                        w + (size_t)(n0 + n) * K + kn + kq * 4);
                }
            }
#pragma unroll
            for (int kk = 0; kk < BK; kk++) {
                float a[8], bb[TN];
                {
                    float4 a0 = *reinterpret_cast<const float4*>(&As[kk * AS_STRIDE + ty * 4]);
                    float4 a1 = *reinterpret_cast<const float4*>(&As[kk * AS_STRIDE + 64 + ty * 4]);
                    a[0] = a0.x; a[1] = a0.y; a[2] = a0.z; a[3] = a0.w;
                    a[4] = a1.x; a[5] = a1.y; a[6] = a1.z; a[7] = a1.w;
                }
#pragma unroll
                for (int t = 0; t < TG; t++) {
                    float4 b4 = *reinterpret_cast<const float4*>(&Bs[kk * BNT + t * 64 + tx * 4]);
                    bb[t * 4 + 0] = b4.x; bb[t * 4 + 1] = b4.y;
                    bb[t * 4 + 2] = b4.z; bb[t * 4 + 3] = b4.w;
                }
#pragma unroll
                for (int i = 0; i < 8; i++)
#pragma unroll
                    for (int j = 0; j < TN; j++)
                        acc[i][j] += a[i] * bb[j];
            }
            __syncthreads();
        }
    } else {
        for (int k0 = 0; k0 < K; k0 += BK) {
#pragma unroll
            for (int j = 0; j < 8; j++) {
                int i = tid + j * 256;
                int m = i & 127, k = i >> 7;
                int kk = k0 + k;
                float v = 0.f;
                if (kk < K) {
                    int s = kk / CIN, c = kk - s * CIN;
                    v = src[sidx[m][s] + c];
                }
                As[k * AS_STRIDE + m] = v;
            }
#pragma unroll
            for (int j = 0; j < (BK * BNT) / 256; j++) {
                int i = tid + j * 256;
                int n = i & (BNT - 1), k = i / BNT;
                int kk = k0 + k;
                float v = 0.f;
                if (kk < K) v = w[(size_t)(n0 + n) * K + kk];
                Bs[k * BNT + n] = v;
            }
            __syncthreads();
#pragma unroll
            for (int kk = 0; kk < BK; kk++) {
                float a[8], bb[TN];
                {
                    float4 a0 = *reinterpret_cast<const float4*>(&As[kk * AS_STRIDE + ty * 4]);
                    float4 a1 = *reinterpret_cast<const float4*>(&As[kk * AS_STRIDE + 64 + ty * 4]);
                    a[0] = a0.x; a[1] = a0.y; a[2] = a0.z; a[3] = a0.w;
                    a[4] = a1.x; a[5] = a1.y; a[6] = a1.z; a[7] = a1.w;
                }
#pragma unroll
                for (int t = 0; t < TG; t++) {
                    float4 b4 = *reinterpret_cast<const float4*>(&Bs[kk * BNT + t * 64 + tx * 4]);
                    bb[t * 4 + 0] = b4.x; bb[t * 4 + 1] = b4.y;
                    bb[t * 4 + 2] = b4.z; bb[t * 4 + 3] = b4.w;
                }
#pragma unroll
                for (int i = 0; i < 8; i++)
#pragma unroll
                    for (int j = 0; j < TN; j++)
                        acc[i][j] += a[i] * bb[j];
            }
            __syncthreads();
        }
    }

    // Store output tile (no bias: cancels in BatchNorm)
#pragma unroll
    for (int i = 0; i < 8; i++) {
        int m = m0 + ((i < 4) ? (ty * 4 + i) : (64 + ty * 4 + (i - 4)));
#pragma unroll
        for (int t = 0; t < TG; t++) {
            float4 o;
            o.x = acc[i][t * 4 + 0];
            o.y = acc[i][t * 4 + 1];
            o.z = acc[i][t * 4 + 2];
            o.w = acc[i][t * 4 + 3];
            *reinterpret_cast<float4*>(&y[(size_t)m * N + n0 + t * 64 + tx * 4]) = o;
        }
    }

    // Fused BN statistics partials
    {
        float s[TN], q[TN];
#pragma unroll
        for (int j = 0; j < TN; j++) { s[j] = 0.f; q[j] = 0.f; }
#pragma unroll
        for (int i = 0; i < 8; i++)
#pragma unroll
            for (int j = 0; j < TN; j++) {
                float v = acc[i][j];
                s[j] += v;
                q[j] += v * v;
            }
        float* ssum = As;
        float* ssq  = Bs;
#pragma unroll
        for (int t = 0; t < TG; t++)
#pragma unroll
            for (int j = 0; j < 4; j++) {
                int col = t * 64 + tx * 4 + j;
                ssum[ty * BNT + col] = s[t * 4 + j];
                ssq [ty * BNT + col] = q[t * 4 + j];
            }
        __syncthreads();
        if (tid < BNT) {
            float S = 0.f, Q = 0.f;
#pragma unroll
            for (int r = 0; r < 16; r++) {
                S += ssum[r * BNT + tid];
                Q += ssq [r * BNT + tid];
            }
            psum[(size_t)blockIdx.x * N + n0 + tid] = S;
            psq [(size_t)blockIdx.x * N + n0 + tid] = Q;
        }
    }
}

// ---------------------------------------------------------------------------
// L3 warp-MMA bf16 GEMM (mma.sync — target-independent, works on sm_103):
//   y[m,n] = sum_{k'} a3[m,k'] * w3i[n,k'],  K' = 3456.
//   a3/w3i carry the fp32->bf16 hi/lo split folded into K:
//   a' = [ahi,ahi,alo], w' = [whi,wlo,whi] per original k.
// CTA tile 128x128, 8 warps (4M x 2N), warp tile 32x64, BK=32.
// SMEM rows padded to 80B: ldmatrix 8-row footprint hits disjoint bank groups.
// ---------------------------------------------------------------------------
#define L3_ROWB 80   // bytes per SMEM row (32 bf16 = 64B + 16B pad)

__device__ __forceinline__ void ldsm_x4(uint32_t& r0, uint32_t& r1,
                                        uint32_t& r2, uint32_t& r3,
                                        uint32_t addr) {
    asm volatile("ldmatrix.sync.aligned.m8n8.x4.shared.b16 {%0,%1,%2,%3}, [%4];"
                 : "=r"(r0), "=r"(r1), "=r"(r2), "=r"(r3) : "r"(addr));
}
__device__ __forceinline__ void mma_bf16(float* d, const uint32_t* a,
                                         const uint32_t* b) {
    asm volatile("mma.sync.aligned.m16n8k16.row.col.f32.bf16.bf16.f32 "
                 "{%0,%1,%2,%3}, {%4,%5,%6,%7}, {%8,%9}, {%0,%1,%2,%3};"
                 : "+f"(d[0]), "+f"(d[1]), "+f"(d[2]), "+f"(d[3])
                 : "r"(a[0]), "r"(a[1]), "r"(a[2]), "r"(a[3]),
                   "r"(b[0]), "r"(b[1]));
}

__global__ __launch_bounds__(256, 2)
void l3_mma_kernel(const __nv_bfloat16* __restrict__ a3,
                   const __nv_bfloat16* __restrict__ wi,
                   const void* __restrict__ spir_raw,
                   float* __restrict__ y) {
    __shared__ __align__(16) char As[128 * L3_ROWB];
    __shared__ __align__(16) char Bs[128 * L3_ROWB];
    __shared__ int s_sidx[128 * NS];

    const int tid = threadIdx.x;
    const int lane = tid & 31;
    const int warp = tid >> 5;
    const int m0 = blockIdx.x * 128;
    const int n0 = blockIdx.y * 128;

    {
        const long long* s64 = (const long long*)spir_raw;
        const int*       s32 = (const int*)spir_raw;
        const int is64 = g_is64;
        for (int j = tid; j < 128 * NS; j += 256) {
            int m = j / NS, s = j - m * NS;
            int gm = m0 + m;
            int b = gm / NV;
            long long e = is64 ? s64[(size_t)gm * NS + s]
                               : (long long)s32[(size_t)gm * NS + s];
            s_sidx[m * NS + s] = (b * NV + (int)e) * 384;
        }
    }
    __syncthreads();

    const int row  = tid >> 1;     // 0..127
    const int half = tid & 1;      // 16-bf16 half of the 32-wide row
    const __nv_bfloat16* wrow = wi + (size_t)(n0 + row) * MKI + half * 16;

    uint4 pa[2], pb[2];
    auto ldg_tile = [&](int k0) {
        int s = k0 / 384, r0 = k0 - s * 384;
        const uint4* ap = reinterpret_cast<const uint4*>(
            a3 + s_sidx[row * NS + s] + r0 + half * 16);
        pa[0] = ap[0];
        pa[1] = ap[1];
        const uint4* bp = reinterpret_cast<const uint4*>(wrow + k0);
        pb[0] = bp[0];
        pb[1] = bp[1];
    };
    ldg_tile(0);

    float acc[2][8][4];
#pragma unroll
    for (int i = 0; i < 2; i++)
#pragma unroll
        for (int j = 0; j < 8; j++)
#pragma unroll
            for (int c = 0; c < 4; c++) acc[i][j][c] = 0.f;

    const int mw = warp >> 1;      // 0..3
    const int nw = warp & 1;       // 0..1
    const uint32_t As_w = smem_u32(As) + mw * 32 * L3_ROWB;
    const uint32_t Bs_w = smem_u32(Bs) + nw * 64 * L3_ROWB;
    const uint32_t lrow = (lane & 15) * L3_ROWB + ((lane >> 4) * 16);
    uint4* sts_a = reinterpret_cast<uint4*>(As + row * L3_ROWB + half * 32);
    uint4* sts_b = reinterpret_cast<uint4*>(Bs + row * L3_ROWB + half * 32);

    for (int k0 = 0; k0 < MKI; k0 += 32) {
        sts_a[0] = pa[0];
        sts_a[1] = pa[1];
        sts_b[0] = pb[0];
        sts_b[1] = pb[1];
        __syncthreads();

        if (k0 + 32 < MKI) ldg_tile(k0 + 32);

#pragma unroll
        for (int ks = 0; ks < 2; ks++) {
            const uint32_t koff = ks * 32;   // bytes
            uint32_t a[2][4];
#pragma unroll
            for (int mf = 0; mf < 2; mf++)
                ldsm_x4(a[mf][0], a[mf][1], a[mf][2], a[mf][3],
                        As_w + mf * 16 * L3_ROWB + lrow + koff);
            uint32_t b[8][2];
#pragma unroll
            for (int nf2 = 0; nf2 < 4; nf2++) {
                uint32_t r0, r1, r2, r3;
                ldsm_x4(r0, r1, r2, r3,
                        Bs_w + nf2 * 16 * L3_ROWB + lrow + koff);
                b[nf2 * 2 + 0][0] = r0;
                b[nf2 * 2 + 1][0] = r1;
                b[nf2 * 2 + 0][1] = r2;
                b[nf2 * 2 + 1][1] = r3;
            }
#pragma unroll
            for (int mf = 0; mf < 2; mf++)
#pragma unroll
                for (int nf = 0; nf < 8; nf++)
                    mma_bf16(acc[mf][nf], a[mf], b[nf]);
        }
        __syncthreads();
    }

    // Epilogue: write fragments to gmem
    const int g = lane >> 2, t = lane & 3;
#pragma unroll
    for (int mf = 0; mf < 2; mf++) {
        const int r0w = m0 + mw * 32 + mf * 16 + g;
#pragma unroll
        for (int nf = 0; nf < 8; nf++) {
            const int col = n0 + nw * 64 + nf * 8 + 2 * t;
            float2 lo = make_float2(acc[mf][nf][0], acc[mf][nf][1]);
            float2 hi = make_float2(acc[mf][nf][2], acc[mf][nf][3]);
            *reinterpret_cast<float2*>(&y[(size_t)r0w * 256 + col]) = lo;
            *reinterpret_cast<float2*>(&y[(size_t)(r0w + 8) * 256 + col]) = hi;
        }
    }
}

// ---------------------------------------------------------------------------
// Pre-split kernels: fp32 -> interleaved bf16 (hi/lo folded into K)
// ---------------------------------------------------------------------------
__global__ void convert_w3_kernel(const float* __restrict__ w,
                                  __nv_bfloat16* __restrict__ wi) {
    int i = blockIdx.x * 256 + threadIdx.x;   // 256*1152 elems
    int n = i / 1152, k = i - n * 1152;
    float v = w[i];
    __nv_bfloat16 h = __float2bfloat16(v);
    __nv_bfloat16 l = __float2bfloat16(v - __bfloat162float(h));
    __nv_bfloat16* o = wi + (size_t)n * MKI + 3 * k;
    o[0] = h;   // pairs a_hi -> hi*hi
    o[1] = l;   // pairs a_hi -> hi*lo
    o[2] = h;   // pairs a_lo -> lo*hi
}

// act = relu(v*scale + shift), split, interleave [hi,hi,lo]
__global__ void convert_act_kernel(const float* __restrict__ in,
                                   const float* __restrict__ scale,
                                   const float* __restrict__ shift,
                                   __nv_bfloat16* __restrict__ a3) {
    int i4 = blockIdx.x * 256 + threadIdx.x;   // MTOT*32 float4s
    int m = i4 >> 5, cq = i4 & 31;
    int cb = cq * 4;
    float4 v  = reinterpret_cast<const float4*>(in)[i4];
    float4 sc = *reinterpret_cast<const float4*>(&scale[cb]);
    float4 sh = *reinterpret_cast<const float4*>(&shift[cb]);
    float a[4];
    a[0] = fmaxf(fmaf(v.x, sc.x, sh.x), 0.f);
    a[1] = fmaxf(fmaf(v.y, sc.y, sh.y), 0.f);
    a[2] = fmaxf(fmaf(v.z, sc.z, sh.z), 0.f);
    a[3] = fmaxf(fmaf(v.w, sc.w, sh.w), 0.f);
    union { __nv_bfloat16 b[12]; uint2 u[3]; } out;
#pragma unroll
    for (int j = 0; j < 4; j++) {
        __nv_bfloat16 h = __float2bfloat16(a[j]);
        __nv_bfloat16 l = __float2bfloat16(a[j] - __bfloat162float(h));
        out.b[3 * j + 0] = h;
        out.b[3 * j + 1] = h;
        out.b[3 * j + 2] = l;
    }
    uint2* dst = reinterpret_cast<uint2*>(a3 + (size_t)m * 384 + cb * 3);
    dst[0] = out.u[0];
    dst[1] = out.u[1];
    dst[2] = out.u[2];
}

// ---------------------------------------------------------------------------
// Standalone BN stats for layer 3: grid (N/32, L3NCH), block (32, 8)
// ---------------------------------------------------------------------------
__global__ void stats_kernel(const float* __restrict__ y,
                             float* __restrict__ psum, float* __restrict__ psq,
                             int N) {
    const int tx = threadIdx.x, ty = threadIdx.y;
    const int o = blockIdx.x * 32 + tx;
    const int rows = MTOT / gridDim.y;
    const int r0 = blockIdx.y * rows;
    float s = 0.f, q = 0.f;
    for (int r = r0 + ty; r < r0 + rows; r += 8) {
        float v = y[(size_t)r * N + o];
        s += v;
        q += v * v;
    }
    __shared__ float shs[8][32], shq[8][32];
    shs[ty][tx] = s;
    shq[ty][tx] = q;
    __syncthreads();
    if (ty == 0) {
#pragma unroll
        for (int i = 1; i < 8; i++) { s += shs[i][tx]; q += shq[i][tx]; }
        psum[(size_t)blockIdx.y * N + o] = s;
        psq [(size_t)blockIdx.y * N + o] = q;
    }
}

// ---------------------------------------------------------------------------
// Reduce partials -> BN scale/shift (fp64, deterministic)
// ---------------------------------------------------------------------------
__global__ void finalize_kernel(const float* __restrict__ psum,
                                const float* __restrict__ psq,
                                const float* __restrict__ g,
                                const float* __restrict__ bt,
                                float* __restrict__ scale,
                                float* __restrict__ shift, int N, int npart) {
    int o = threadIdx.x;
    if (o >= N) return;
    double s = 0.0, q = 0.0;
    for (int c = 0; c < npart; c++) {
        s += psum[(size_t)c * N + o];
        q += psq [(size_t)c * N + o];
    }
    double mean = s / (double)MTOT;
    double var  = q / (double)MTOT - mean * mean;
    float sc = g[o] * rsqrtf((float)var + 1e-5f);
    scale[o] = sc;
    shift[o] = bt[o] - (float)mean * sc;
}

// Max over vertices with fused BN+ReLU
__global__ void maxpool_kernel(const float* __restrict__ act,
                               const float* __restrict__ scale,
                               const float* __restrict__ shift,
                               float* __restrict__ hmax) {
    const int tx = threadIdx.x, ty = threadIdx.y;
    const int o = blockIdx.x * 32 + tx;
    const int b = blockIdx.y;
    const float sc = scale[o], sh = shift[o];
    float m = -1e30f;
    for (int v = ty; v < NV; v += 8)
        m = fmaxf(m, fmaf(act[((size_t)b * NV + v) * 256 + o], sc, sh));
    __shared__ float shm[8][32];
    shm[ty][tx] = m;
    __syncthreads();
    if (ty == 0) {
#pragma unroll
        for (int i = 1; i < 8; i++) m = fmaxf(m, shm[i][tx]);
        hmax[b * 256 + o] = fmaxf(m, 0.f);
    }
}

__global__ void final_linear_kernel(const float* __restrict__ hmax,
                                    const float* __restrict__ pw,
                                    const float* __restrict__ pb,
                                    float* __restrict__ out) {
    __shared__ float sh[BATCH * 256];
    for (int i = threadIdx.x; i < BATCH * 256; i += 256) sh[i] = hmax[i];
    __syncthreads();
    int j = threadIdx.x;
    float acc[BATCH];
#pragma unroll
    for (int b = 0; b < BATCH; b++) acc[b] = pb[j];
    for (int o = 0; o < 256; o++) {
        float wv = pw[j * 256 + o];
#pragma unroll
        for (int b = 0; b < BATCH; b++) acc[b] += sh[b * 256 + o] * wv;
    }
#pragma unroll
    for (int b = 0; b < BATCH; b++) out[b * 256 + j] = acc[b];
}

// ---------------------------------------------------------------------------
extern "C" void kernel_launch(void* const* d_in, const int* in_sizes, int n_in,
                              void* d_out, int out_size) {
    const float* x    = (const float*)d_in[0];
    const void*  spir = d_in[1];
    const float* w1 = (const float*)d_in[2];
    const float* g1 = (const float*)d_in[4];
    const float* t1 = (const float*)d_in[5];
    const float* w2 = (const float*)d_in[6];
    const float* g2 = (const float*)d_in[8];
    const float* t2 = (const float*)d_in[9];
    const float* w3 = (const float*)d_in[10];
    const float* g3 = (const float*)d_in[12];
    const float* t3 = (const float*)d_in[13];
    const float* pw = (const float*)d_in[14];
    const float* pb = (const float*)d_in[15];

    float *bufA, *bufB, *psum, *psq, *scale, *shift, *hmax;
    __nv_bfloat16 *a3, *w3i;
    cudaGetSymbolAddress((void**)&bufA,  g_bufA);
    cudaGetSymbolAddress((void**)&bufB,  g_bufB);
    cudaGetSymbolAddress((void**)&psum,  g_psum);
    cudaGetSymbolAddress((void**)&psq,   g_psq);
    cudaGetSymbolAddress((void**)&scale, g_scale);
    cudaGetSymbolAddress((void**)&shift, g_shift);
    cudaGetSymbolAddress((void**)&hmax,  g_hmax);
    cudaGetSymbolAddress((void**)&a3,    g_a3);
    cudaGetSymbolAddress((void**)&w3i,   g_w3i);

    detect64_kernel<<<1, 256>>>((const long long*)spir);
    convert_w3_kernel<<<(256 * 1152) / 256, 256>>>(w3, w3i);

    const int mblocks = MTOT / BM;   // 750

    // ---- Layer 1: 3 -> 64, SIMT ----
    gemm_gather_kernel<3, false, 64, false><<<dim3(mblocks, 1), 256>>>(
        x, spir, w1, nullptr, nullptr, bufA, psum, psq, 64);
    finalize_kernel<<<1, 64>>>(psum, psq, g1, t1, scale, shift, 64, NPART);

    // ---- Layer 2: 64 -> 128, SIMT, BN1+ReLU fused ----
    gemm_gather_kernel<64, true, 128, true><<<dim3(mblocks, 1), 256>>>(
        bufA, spir, w2, scale, shift, bufB, psum, psq, 128);
    finalize_kernel<<<1, 128>>>(psum, psq, g2, t2, scale, shift, 128, NPART);

    // ---- Layer 3: 128 -> 256, warp-MMA bf16 split GEMM ----
    convert_act_kernel<<<(MTOT * 32) / 256, 256>>>(bufB, scale, shift, a3);
    l3_mma_kernel<<<dim3(mblocks, 2), 256>>>(a3, w3i, spir, bufA);
    stats_kernel<<<dim3(8, L3NCH), dim3(32, 8)>>>(bufA, psum, psq, 256);
    finalize_kernel<<<1, 256>>>(psum, psq, g3, t3, scale, shift, 256, L3NCH);

    // ---- Max pool (BN3+ReLU fused) + final linear ----
    maxpool_kernel<<<dim3(8, BATCH), dim3(32, 8)>>>(bufA, scale, shift, hmax);
    final_linear_kernel<<<1, 256>>>(hmax, pw, pb, (float*)d_out);
}

// round 13
// speedup vs baseline: 1.8702x; 1.2777x over previous
#include <cuda_runtime.h>
#include <cuda_bf16.h>
#include <cstdint>
#include <cstddef>
#include <cstring>

// Problem constants
#define BATCH 8
#define NV    12000
#define NS    9
#define MTOT  (BATCH * NV)   // 96000
#define NPART (MTOT / 128)   // 750 m-blocks -> stats partials (SIMT L1)
#define L3NCH 120            // chunks for standalone stats passes

// Scratch (device globals; no allocation allowed)
__device__ float g_bufA[(size_t)MTOT * 256];          // 98.3 MB
__device__ float g_bufB[(size_t)MTOT * 128];          // 49.2 MB
__device__ __nv_bfloat16 g_a3[(size_t)MTOT * 384];    // 73.7 MB (hi,hi,lo interleave)
__device__ __nv_bfloat16 g_w3i[256 * 3 * 1152];       // 1.77 MB
__device__ __nv_bfloat16 g_w2i[128 * 3 * 576];        // 0.44 MB
__device__ float g_psum[NPART * 256];
__device__ float g_psq [NPART * 256];
__device__ float g_scale[256];
__device__ float g_shift[256];
__device__ float g_hmax[BATCH * 256];
__device__ int   g_is64;

__device__ __forceinline__ uint32_t smem_u32(const void* p) {
    uint32_t a;
    asm("{ .reg .u64 t; cvta.to.shared.u64 t, %1; cvt.u32.u64 %0, t; }"
        : "=r"(a) : "l"(p));
    return a;
}

// ---------------------------------------------------------------------------
// Detect whether the spiral index tensor is int64 or int32.
// ---------------------------------------------------------------------------
__global__ void detect64_kernel(const long long* __restrict__ p) {
    bool ok = true;
    for (int i = threadIdx.x; i < 2048; i += 256) {
        long long v = p[i];
        if (v < 0 || v >= NV) ok = false;
    }
    int all = __syncthreads_and(ok ? 1 : 0);
    if (threadIdx.x == 0) g_is64 = all;
}

// ---------------------------------------------------------------------------
// SIMT gather-fused SGEMM (R5-proven) — layer 1 only (K = 27).
// ---------------------------------------------------------------------------
#define BM 128
#define BK 16
#define AS_STRIDE (BM + 4)

template <int CIN, int BNT>
__global__ __launch_bounds__(256, 2)
void gemm_gather_kernel(const float* __restrict__ src,
                        const void* __restrict__ spir_raw,
                        const float* __restrict__ w,
                        float* __restrict__ y,
                        float* __restrict__ psum,
                        float* __restrict__ psq,
                        int N) {
    constexpr int K   = NS * CIN;
    constexpr int TN  = BNT / 16;
    constexpr int TG  = TN / 4;
    __shared__ float As[BK * AS_STRIDE];
    __shared__ float Bs[BK * BNT];
    __shared__ int   sidx[BM][NS];

    const int tid = threadIdx.x;
    const int tx = tid & 15;
    const int ty = tid >> 4;
    const int m0 = blockIdx.x * BM;
    const int n0 = blockIdx.y * BNT;

    {
        const long long* s64 = (const long long*)spir_raw;
        const int*       s32 = (const int*)spir_raw;
        const int is64 = g_is64;
        for (int j = tid; j < BM * NS; j += 256) {
            int m = j / NS, s = j - m * NS;
            int gm = m0 + m;
            int b = gm / NV;
            long long e = is64 ? s64[(size_t)gm * NS + s]
                               : (long long)s32[(size_t)gm * NS + s];
            sidx[m][s] = (b * NV + (int)e) * CIN;
        }
    }
    __syncthreads();

    float acc[8][TN];
#pragma unroll
    for (int i = 0; i < 8; i++)
#pragma unroll
        for (int j = 0; j < TN; j++) acc[i][j] = 0.f;

    for (int k0 = 0; k0 < K; k0 += BK) {
#pragma unroll
        for (int j = 0; j < 8; j++) {
            int i = tid + j * 256;
            int m = i & 127, k = i >> 7;
            int kk = k0 + k;
            float v = 0.f;
            if (kk < K) {
                int s = kk / CIN, c = kk - s * CIN;
                v = src[sidx[m][s] + c];
            }
            As[k * AS_STRIDE + m] = v;
        }
#pragma unroll
        for (int j = 0; j < (BK * BNT) / 256; j++) {
            int i = tid + j * 256;
            int n = i & (BNT - 1), k = i / BNT;
            int kk = k0 + k;
            float v = 0.f;
            if (kk < K) v = w[(size_t)(n0 + n) * K + kk];
            Bs[k * BNT + n] = v;
        }
        __syncthreads();
#pragma unroll
        for (int kk = 0; kk < BK; kk++) {
            float a[8], bb[TN];
            {
                float4 a0 = *reinterpret_cast<const float4*>(&As[kk * AS_STRIDE + ty * 4]);
                float4 a1 = *reinterpret_cast<const float4*>(&As[kk * AS_STRIDE + 64 + ty * 4]);
                a[0] = a0.x; a[1] = a0.y; a[2] = a0.z; a[3] = a0.w;
                a[4] = a1.x; a[5] = a1.y; a[6] = a1.z; a[7] = a1.w;
            }
#pragma unroll
            for (int t = 0; t < TG; t++) {
                float4 b4 = *reinterpret_cast<const float4*>(&Bs[kk * BNT + t * 64 + tx * 4]);
                bb[t * 4 + 0] = b4.x; bb[t * 4 + 1] = b4.y;
                bb[t * 4 + 2] = b4.z; bb[t * 4 + 3] = b4.w;
            }
#pragma unroll
            for (int i = 0; i < 8; i++)
#pragma unroll
                for (int j = 0; j < TN; j++)
                    acc[i][j] += a[i] * bb[j];
        }
        __syncthreads();
    }

    // Store output tile (no bias: cancels in BatchNorm)
#pragma unroll
    for (int i = 0; i < 8; i++) {
        int m = m0 + ((i < 4) ? (ty * 4 + i) : (64 + ty * 4 + (i - 4)));
#pragma unroll
        for (int t = 0; t < TG; t++) {
            float4 o;
            o.x = acc[i][t * 4 + 0];
            o.y = acc[i][t * 4 + 1];
            o.z = acc[i][t * 4 + 2];
            o.w = acc[i][t * 4 + 3];
            *reinterpret_cast<float4*>(&y[(size_t)m * N + n0 + t * 64 + tx * 4]) = o;
        }
    }

    // Fused BN statistics partials
    {
        float s[TN], q[TN];
#pragma unroll
        for (int j = 0; j < TN; j++) { s[j] = 0.f; q[j] = 0.f; }
#pragma unroll
        for (int i = 0; i < 8; i++)
#pragma unroll
            for (int j = 0; j < TN; j++) {
                float v = acc[i][j];
                s[j] += v;
                q[j] += v * v;
            }
        float* ssum = As;
        float* ssq  = Bs;
#pragma unroll
        for (int t = 0; t < TG; t++)
#pragma unroll
            for (int j = 0; j < 4; j++) {
                int col = t * 64 + tx * 4 + j;
                ssum[ty * BNT + col] = s[t * 4 + j];
                ssq [ty * BNT + col] = q[t * 4 + j];
            }
        __syncthreads();
        if (tid < BNT) {
            float S = 0.f, Q = 0.f;
#pragma unroll
            for (int r = 0; r < 16; r++) {
                S += ssum[r * BNT + tid];
                Q += ssq [r * BNT + tid];
            }
            psum[(size_t)blockIdx.x * N + n0 + tid] = S;
            psq [(size_t)blockIdx.x * N + n0 + tid] = Q;
        }
    }
}

// ---------------------------------------------------------------------------
// Warp-MMA bf16 split-GEMM (mma.sync; R10-proven for L3, generalized to L2):
//   y[m,n] = sum_{k'} a3[m,k'] * wi[n,k'],  K' = 3*NS*CIN.
//   a' = [ahi,ahi,alo], w' = [whi,wlo,whi] per original k (lo*lo dropped).
// CTA tile 128x128, 8 warps (4M x 2N), warp tile 32x64, BK=32.
// ---------------------------------------------------------------------------
#define L3_ROWB 80   // bytes per SMEM row (32 bf16 = 64B + 16B pad)

__device__ __forceinline__ void ldsm_x4(uint32_t& r0, uint32_t& r1,
                                        uint32_t& r2, uint32_t& r3,
                                        uint32_t addr) {
    asm volatile("ldmatrix.sync.aligned.m8n8.x4.shared.b16 {%0,%1,%2,%3}, [%4];"
                 : "=r"(r0), "=r"(r1), "=r"(r2), "=r"(r3) : "r"(addr));
}
__device__ __forceinline__ void mma_bf16(float* d, const uint32_t* a,
                                         const uint32_t* b) {
    asm volatile("mma.sync.aligned.m16n8k16.row.col.f32.bf16.bf16.f32 "
                 "{%0,%1,%2,%3}, {%4,%5,%6,%7}, {%8,%9}, {%0,%1,%2,%3};"
                 : "+f"(d[0]), "+f"(d[1]), "+f"(d[2]), "+f"(d[3])
                 : "r"(a[0]), "r"(a[1]), "r"(a[2]), "r"(a[3]),
                   "r"(b[0]), "r"(b[1]));
}

template <int CIN, int NOUT>
__global__ __launch_bounds__(256, 2)
void mma_gemm_kernel(const __nv_bfloat16* __restrict__ a3,
                     const __nv_bfloat16* __restrict__ wi,
                     const void* __restrict__ spir_raw,
                     float* __restrict__ y) {
    constexpr int AROW = 3 * CIN;        // interleaved elems per neighbor row
    constexpr int KI   = AROW * NS;      // total interleaved K
    __shared__ __align__(16) char As[128 * L3_ROWB];
    __shared__ __align__(16) char Bs[128 * L3_ROWB];
    __shared__ int s_sidx[128 * NS];

    const int tid = threadIdx.x;
    const int lane = tid & 31;
    const int warp = tid >> 5;
    const int m0 = blockIdx.x * 128;
    const int n0 = blockIdx.y * 128;

    {
        const long long* s64 = (const long long*)spir_raw;
        const int*       s32 = (const int*)spir_raw;
        const int is64 = g_is64;
        for (int j = tid; j < 128 * NS; j += 256) {
            int m = j / NS, s = j - m * NS;
            int gm = m0 + m;
            int b = gm / NV;
            long long e = is64 ? s64[(size_t)gm * NS + s]
                               : (long long)s32[(size_t)gm * NS + s];
            s_sidx[m * NS + s] = (b * NV + (int)e) * AROW;
        }
    }
    __syncthreads();

    const int row  = tid >> 1;     // 0..127
    const int half = tid & 1;      // 16-bf16 half of the 32-wide row chunk
    const __nv_bfloat16* wrow = wi + (size_t)(n0 + row) * KI + half * 16;

    uint4 pa[2], pb[2];
    auto ldg_tile = [&](int k0) {
        int s = k0 / AROW, r0 = k0 - s * AROW;
        const uint4* ap = reinterpret_cast<const uint4*>(
            a3 + s_sidx[row * NS + s] + r0 + half * 16);
        pa[0] = ap[0];
        pa[1] = ap[1];
        const uint4* bp = reinterpret_cast<const uint4*>(wrow + k0);
        pb[0] = bp[0];
        pb[1] = bp[1];
    };
    ldg_tile(0);

    float acc[2][8][4];
#pragma unroll
    for (int i = 0; i < 2; i++)
#pragma unroll
        for (int j = 0; j < 8; j++)
#pragma unroll
            for (int c = 0; c < 4; c++) acc[i][j][c] = 0.f;

    const int mw = warp >> 1;      // 0..3
    const int nw = warp & 1;       // 0..1
    const uint32_t As_w = smem_u32(As) + mw * 32 * L3_ROWB;
    const uint32_t Bs_w = smem_u32(Bs) + nw * 64 * L3_ROWB;
    const uint32_t lrow = (lane & 15) * L3_ROWB + ((lane >> 4) * 16);
    uint4* sts_a = reinterpret_cast<uint4*>(As + row * L3_ROWB + half * 32);
    uint4* sts_b = reinterpret_cast<uint4*>(Bs + row * L3_ROWB + half * 32);

    for (int k0 = 0; k0 < KI; k0 += 32) {
        sts_a[0] = pa[0];
        sts_a[1] = pa[1];
        sts_b[0] = pb[0];
        sts_b[1] = pb[1];
        __syncthreads();

        if (k0 + 32 < KI) ldg_tile(k0 + 32);

#pragma unroll
        for (int ks = 0; ks < 2; ks++) {
            const uint32_t koff = ks * 32;   // bytes
            uint32_t a[2][4];
#pragma unroll
            for (int mf = 0; mf < 2; mf++)
                ldsm_x4(a[mf][0], a[mf][1], a[mf][2], a[mf][3],
                        As_w + mf * 16 * L3_ROWB + lrow + koff);
            uint32_t b[8][2];
#pragma unroll
            for (int nf2 = 0; nf2 < 4; nf2++) {
                uint32_t r0, r1, r2, r3;
                ldsm_x4(r0, r1, r2, r3,
                        Bs_w + nf2 * 16 * L3_ROWB + lrow + koff);
                b[nf2 * 2 + 0][0] = r0;
                b[nf2 * 2 + 1][0] = r1;
                b[nf2 * 2 + 0][1] = r2;
                b[nf2 * 2 + 1][1] = r3;
            }
#pragma unroll
            for (int mf = 0; mf < 2; mf++)
#pragma unroll
                for (int nf = 0; nf < 8; nf++)
                    mma_bf16(acc[mf][nf], a[mf], b[nf]);
        }
        __syncthreads();
    }

    // Epilogue: write fragments to gmem
    const int g = lane >> 2, t = lane & 3;
#pragma unroll
    for (int mf = 0; mf < 2; mf++) {
        const int r0w = m0 + mw * 32 + mf * 16 + g;
#pragma unroll
        for (int nf = 0; nf < 8; nf++) {
            const int col = n0 + nw * 64 + nf * 8 + 2 * t;
            float2 lo = make_float2(acc[mf][nf][0], acc[mf][nf][1]);
            float2 hi = make_float2(acc[mf][nf][2], acc[mf][nf][3]);
            *reinterpret_cast<float2*>(&y[(size_t)r0w * NOUT + col]) = lo;
            *reinterpret_cast<float2*>(&y[(size_t)(r0w + 8) * NOUT + col]) = hi;
        }
    }
}

// ---------------------------------------------------------------------------
// Pre-split kernels: fp32 -> interleaved bf16 (hi/lo folded into K)
// ---------------------------------------------------------------------------
template <int K>
__global__ void convert_w_kernel(const float* __restrict__ w,
                                 __nv_bfloat16* __restrict__ wi) {
    int i = blockIdx.x * 256 + threadIdx.x;
    int n = i / K, k = i - n * K;
    float v = w[i];
    __nv_bfloat16 h = __float2bfloat16(v);
    __nv_bfloat16 l = __float2bfloat16(v - __bfloat162float(h));
    __nv_bfloat16* o = wi + (size_t)n * (3 * K) + 3 * k;
    o[0] = h;   // pairs a_hi -> hi*hi
    o[1] = l;   // pairs a_hi -> hi*lo
    o[2] = h;   // pairs a_lo -> lo*hi
}

// act = relu(v*scale + shift), split, interleave [hi,hi,lo]
template <int CIN>
__global__ void convert_act_kernel(const float* __restrict__ in,
                                   const float* __restrict__ scale,
                                   const float* __restrict__ shift,
                                   __nv_bfloat16* __restrict__ a3) {
    int i4 = blockIdx.x * 256 + threadIdx.x;   // MTOT*CIN/4 float4s
    int m = i4 / (CIN / 4), cq = i4 & (CIN / 4 - 1);
    int cb = cq * 4;
    float4 v  = reinterpret_cast<const float4*>(in)[i4];
    float4 sc = *reinterpret_cast<const float4*>(&scale[cb]);
    float4 sh = *reinterpret_cast<const float4*>(&shift[cb]);
    float a[4];
    a[0] = fmaxf(fmaf(v.x, sc.x, sh.x), 0.f);
    a[1] = fmaxf(fmaf(v.y, sc.y, sh.y), 0.f);
    a[2] = fmaxf(fmaf(v.z, sc.z, sh.z), 0.f);
    a[3] = fmaxf(fmaf(v.w, sc.w, sh.w), 0.f);
    union { __nv_bfloat16 b[12]; uint2 u[3]; } out;
#pragma unroll
    for (int j = 0; j < 4; j++) {
        __nv_bfloat16 h = __float2bfloat16(a[j]);
        __nv_bfloat16 l = __float2bfloat16(a[j] - __bfloat162float(h));
        out.b[3 * j + 0] = h;
        out.b[3 * j + 1] = h;
        out.b[3 * j + 2] = l;
    }
    uint2* dst = reinterpret_cast<uint2*>(a3 + (size_t)m * (3 * CIN) + cb * 3);
    dst[0] = out.u[0];
    dst[1] = out.u[1];
    dst[2] = out.u[2];
}

// ---------------------------------------------------------------------------
// Standalone BN stats: grid (N/32, L3NCH), block (32, 8)
// ---------------------------------------------------------------------------
__global__ void stats_kernel(const float* __restrict__ y,
                             float* __restrict__ psum, float* __restrict__ psq,
                             int N) {
    const int tx = threadIdx.x, ty = threadIdx.y;
    const int o = blockIdx.x * 32 + tx;
    const int rows = MTOT / gridDim.y;
    const int r0 = blockIdx.y * rows;
    float s = 0.f, q = 0.f;
    for (int r = r0 + ty; r < r0 + rows; r += 8) {
        float v = y[(size_t)r * N + o];
        s += v;
        q += v * v;
    }
    __shared__ float shs[8][32], shq[8][32];
    shs[ty][tx] = s;
    shq[ty][tx] = q;
    __syncthreads();
    if (ty == 0) {
#pragma unroll
        for (int i = 1; i < 8; i++) { s += shs[i][tx]; q += shq[i][tx]; }
        psum[(size_t)blockIdx.y * N + o] = s;
        psq [(size_t)blockIdx.y * N + o] = q;
    }
}

// ---------------------------------------------------------------------------
// Reduce partials -> BN scale/shift. PARALLEL (R10 ncu: the serial 1-block
// finalize was 141.7us x3 — the top launch). One block per channel, fp64
// strided sums + fixed-order tree (deterministic).
// ---------------------------------------------------------------------------
__global__ void finalize_kernel(const float* __restrict__ psum,
                                const float* __restrict__ psq,
                                const float* __restrict__ g,
                                const float* __restrict__ bt,
                                float* __restrict__ scale,
                                float* __restrict__ shift, int N, int npart) {
    const int o = blockIdx.x;     // channel
    const int t = threadIdx.x;    // 256 threads
    double s = 0.0, q = 0.0;
    for (int c = t; c < npart; c += 256) {
        s += psum[(size_t)c * N + o];
        q += psq [(size_t)c * N + o];
    }
    __shared__ double ss[256], sq[256];
    ss[t] = s;
    sq[t] = q;
    __syncthreads();
#pragma unroll
    for (int st = 128; st > 0; st >>= 1) {
        if (t < st) {
            ss[t] += ss[t + st];
            sq[t] += sq[t + st];
        }
        __syncthreads();
    }
    if (t == 0) {
        double mean = ss[0] / (double)MTOT;
        double var  = sq[0] / (double)MTOT - mean * mean;
        float sc = g[o] * rsqrtf((float)var + 1e-5f);
        scale[o] = sc;
        shift[o] = bt[o] - (float)mean * sc;
    }
}

// Max over vertices with fused BN+ReLU
__global__ void maxpool_kernel(const float* __restrict__ act,
                               const float* __restrict__ scale,
                               const float* __restrict__ shift,
                               float* __restrict__ hmax) {
    const int tx = threadIdx.x, ty = threadIdx.y;
    const int o = blockIdx.x * 32 + tx;
    const int b = blockIdx.y;
    const float sc = scale[o], sh = shift[o];
    float m = -1e30f;
    for (int v = ty; v < NV; v += 8)
        m = fmaxf(m, fmaf(act[((size_t)b * NV + v) * 256 + o], sc, sh));
    __shared__ float shm[8][32];
    shm[ty][tx] = m;
    __syncthreads();
    if (ty == 0) {
#pragma unroll
        for (int i = 1; i < 8; i++) m = fmaxf(m, shm[i][tx]);
        hmax[b * 256 + o] = fmaxf(m, 0.f);
    }
}

__global__ void final_linear_kernel(const float* __restrict__ hmax,
                                    const float* __restrict__ pw,
                                    const float* __restrict__ pb,
                                    float* __restrict__ out) {
    __shared__ float sh[BATCH * 256];
    for (int i = threadIdx.x; i < BATCH * 256; i += 256) sh[i] = hmax[i];
    __syncthreads();
    int j = threadIdx.x;
    float acc[BATCH];
#pragma unroll
    for (int b = 0; b < BATCH; b++) acc[b] = pb[j];
    for (int o = 0; o < 256; o++) {
        float wv = pw[j * 256 + o];
#pragma unroll
        for (int b = 0; b < BATCH; b++) acc[b] += sh[b * 256 + o] * wv;
    }
#pragma unroll
    for (int b = 0; b < BATCH; b++) out[b * 256 + j] = acc[b];
}

// ---------------------------------------------------------------------------
extern "C" void kernel_launch(void* const* d_in, const int* in_sizes, int n_in,
                              void* d_out, int out_size) {
    const float* x    = (const float*)d_in[0];
    const void*  spir = d_in[1];
    const float* w1 = (const float*)d_in[2];
    const float* g1 = (const float*)d_in[4];
    const float* t1 = (const float*)d_in[5];
    const float* w2 = (const float*)d_in[6];
    const float* g2 = (const float*)d_in[8];
    const float* t2 = (const float*)d_in[9];
    const float* w3 = (const float*)d_in[10];
    const float* g3 = (const float*)d_in[12];
    const float* t3 = (const float*)d_in[13];
    const float* pw = (const float*)d_in[14];
    const float* pb = (const float*)d_in[15];

    float *bufA, *bufB, *psum, *psq, *scale, *shift, *hmax;
    __nv_bfloat16 *a3, *w3i, *w2i;
    cudaGetSymbolAddress((void**)&bufA,  g_bufA);
    cudaGetSymbolAddress((void**)&bufB,  g_bufB);
    cudaGetSymbolAddress((void**)&psum,  g_psum);
    cudaGetSymbolAddress((void**)&psq,   g_psq);
    cudaGetSymbolAddress((void**)&scale, g_scale);
    cudaGetSymbolAddress((void**)&shift, g_shift);
    cudaGetSymbolAddress((void**)&hmax,  g_hmax);
    cudaGetSymbolAddress((void**)&a3,    g_a3);
    cudaGetSymbolAddress((void**)&w3i,   g_w3i);
    cudaGetSymbolAddress((void**)&w2i,   g_w2i);

    detect64_kernel<<<1, 256>>>((const long long*)spir);
    convert_w_kernel<1152><<<(256 * 1152) / 256, 256>>>(w3, w3i);
    convert_w_kernel<576><<<(128 * 576) / 256, 256>>>(w2, w2i);

    const int mblocks = MTOT / BM;   // 750

    // ---- Layer 1: 3 -> 64, SIMT with fused stats ----
    gemm_gather_kernel<3, 64><<<dim3(mblocks, 1), 256>>>(
        x, spir, w1, bufA, psum, psq, 64);
    finalize_kernel<<<64, 256>>>(psum, psq, g1, t1, scale, shift, 64, NPART);

    // ---- Layer 2: 64 -> 128, warp-MMA bf16 split GEMM ----
    convert_act_kernel<64><<<(MTOT * 16) / 256, 256>>>(bufA, scale, shift, a3);
    mma_gemm_kernel<64, 128><<<dim3(mblocks, 1), 256>>>(a3, w2i, spir, bufB);
    stats_kernel<<<dim3(4, L3NCH), dim3(32, 8)>>>(bufB, psum, psq, 128);
    finalize_kernel<<<128, 256>>>(psum, psq, g2, t2, scale, shift, 128, L3NCH);

    // ---- Layer 3: 128 -> 256, warp-MMA bf16 split GEMM ----
    convert_act_kernel<128><<<(MTOT * 32) / 256, 256>>>(bufB, scale, shift, a3);
    mma_gemm_kernel<128, 256><<<dim3(mblocks, 2), 256>>>(a3, w3i, spir, bufA);
    stats_kernel<<<dim3(8, L3NCH), dim3(32, 8)>>>(bufA, psum, psq, 256);
    finalize_kernel<<<256, 256>>>(psum, psq, g3, t3, scale, shift, 256, L3NCH);

    // ---- Max pool (BN3+ReLU fused) + final linear ----
    maxpool_kernel<<<dim3(8, BATCH), dim3(32, 8)>>>(bufA, scale, shift, hmax);
    final_linear_kernel<<<1, 256>>>(hmax, pw, pb, (float*)d_out);
}